// round 13
// baseline (speedup 1.0000x reference)
#include <cuda_runtime.h>
#include <math.h>

// Problem constants
#define Nn 50000
#define Ee 800000
#define IND 9
#define HIDD 128
#define Gg 256
#define OUTD 10
#define CLUST 20
#define EPSv 1e-5f
#define SBANK 8
#define NB 392   // ceil(Nn/128)

// ---------------- scratch (device globals; no allocation allowed) ----------------
__device__ float  g_h[(Nn + 1) * HIDD];  // GEMM output * dinv (+r); row Nn = zeros
__device__ float  g_act[Nn * HIDD];      // rational output (pre-BN)
__device__ int    g_cnt[Nn];
__device__ int    g_rank[Ee];
__device__ int    g_rowptr[Nn + 1];
__device__ int    g_csr[Ee];             // per dst-sorted edge: src only
__device__ float  g_dinv[Nn];
__device__ int    g_bsum[NB];
__device__ int    g_boff[NB];
__device__ double g_sum[SBANK * HIDD];   // banked to cut atomic contention
__device__ double g_sq[SBANK * HIDD];
__device__ float  g_a[HIDD];
__device__ float  g_c[HIDD];
__device__ float  g_pooled[Gg * HIDD];
__device__ float  g_z1[Gg * HIDD];
__device__ float  g_z2[Gg * HIDD];

// ---------------- f32x2 packed-FMA helpers ----------------
__device__ __forceinline__ unsigned long long pack2_dup(float x) {
    unsigned long long r;
    asm("mov.b64 %0, {%1, %1};" : "=l"(r) : "f"(x));
    return r;
}
__device__ __forceinline__ void ffma2(unsigned long long& d, unsigned long long a,
                                      unsigned long long b) {
    asm("fma.rn.f32x2 %0, %1, %2, %0;" : "+l"(d) : "l"(a), "l"(b));
}
__device__ __forceinline__ float2 ull2f2(unsigned long long u) {
    float2 f;
    asm("mov.b64 {%0, %1}, %2;" : "=f"(f.x), "=f"(f.y) : "l"(u));
    return f;
}

// ---------------- precompute kernels ----------------
__global__ void init_kernel() {
    int i = blockIdx.x * blockDim.x + threadIdx.x;
    if (i < Nn) g_cnt[i] = 0;
    if (i < SBANK * HIDD) { g_sum[i] = 0.0; g_sq[i] = 0.0; }
    if (i < HIDD) g_h[Nn * HIDD + i] = 0.f;   // zero pad row
}

__global__ void hist_kernel(const int* __restrict__ ei) {
    int e = blockIdx.x * blockDim.x + threadIdx.x;
    if (e < Ee) g_rank[e] = atomicAdd(&g_cnt[ei[Ee + e]], 1);
}

// phase 1: per-128-chunk sums
__global__ void bsum_kernel() {
    int idx = blockIdx.x * 128 + threadIdx.x;
    int c = (idx < Nn) ? g_cnt[idx] : 0;
    #pragma unroll
    for (int o = 16; o; o >>= 1) c += __shfl_xor_sync(0xffffffffu, c, o);
    __shared__ int ws[4];
    if ((threadIdx.x & 31) == 0) ws[threadIdx.x >> 5] = c;
    __syncthreads();
    if (threadIdx.x == 0) g_bsum[blockIdx.x] = ws[0] + ws[1] + ws[2] + ws[3];
}

// phase 2: single-block exclusive scan of NB block sums
__global__ void bscan_kernel() {
    __shared__ int s[512];
    int t = threadIdx.x;
    int v = (t < NB) ? g_bsum[t] : 0;
    s[t] = v; __syncthreads();
    for (int off = 1; off < 512; off <<= 1) {
        int u = (t >= off) ? s[t - off] : 0;
        __syncthreads();
        s[t] += u;
        __syncthreads();
    }
    if (t < NB) g_boff[t] = s[t] - v;
}

// phase 3: block-local exclusive scan + global offset -> rowptr; also dinv
__global__ void rowptr_kernel() {
    __shared__ int ws[4];
    int t = threadIdx.x;
    int idx = blockIdx.x * 128 + t;
    int c = (idx < Nn) ? g_cnt[idx] : 0;
    int lane = t & 31, w = t >> 5;
    int inc = c;
    #pragma unroll
    for (int o = 1; o < 32; o <<= 1) {
        int u = __shfl_up_sync(0xffffffffu, inc, o);
        if (lane >= o) inc += u;
    }
    if (lane == 31) ws[w] = inc;
    __syncthreads();
    int wo = 0;
    #pragma unroll
    for (int i = 0; i < 4; i++) wo += (i < w) ? ws[i] : 0;
    int excl = g_boff[blockIdx.x] + wo + inc - c;
    if (idx < Nn) {
        g_rowptr[idx] = excl;
        g_dinv[idx] = rsqrtf((float)c + 1.0f);
    }
    if (blockIdx.x == 0 && t == 0) g_rowptr[Nn] = Ee;
}

// fill CSR (src only); rank from hist
__global__ void fill_kernel(const int* __restrict__ ei) {
    int e = blockIdx.x * blockDim.x + threadIdx.x;
    if (e < Ee) {
        int d = ei[Ee + e];
        g_csr[g_rowptr[d] + g_rank[e]] = ei[e];
    }
}

// ---------------- GEMM layer 0: h' = dinv * (x(N,9) @ W0(9,128)) ----------------
__global__ void gemm0_kernel(const float* __restrict__ x, const float* __restrict__ W0) {
    __shared__ float sW[IND * HIDD];
    for (int i = threadIdx.x; i < IND * HIDD; i += blockDim.x) sW[i] = W0[i];
    __syncthreads();
    int j = threadIdx.x & 127;
    int rpb = blockDim.x >> 7; // 2
    int r0 = blockIdx.x * rpb + (threadIdx.x >> 7);
    for (int n = r0; n < Nn; n += gridDim.x * rpb) {
        float acc = 0.f;
        #pragma unroll
        for (int k = 0; k < IND; k++) acc = fmaf(x[n * IND + k], sW[k * HIDD + j], acc);
        g_h[n * HIDD + j] = acc * g_dinv[n];
    }
}

// ---- SGEMM (f32x2): g_h = dinv_row * ((act * a_row) @ W + r),  r = c @ W ----
#define GBK 32
__global__ __launch_bounds__(256, 2) void gemm_kernel(const float* __restrict__ W) {
    __shared__ float Ast[GBK * 132]; // transposed A chunk [k][row], pad 132
    __shared__ float Ws[GBK * 128];  // B chunk [k][j], pre-scaled by a[k]
    __shared__ float sa[HIDD], sc[HIDD], sdv[HIDD];
    __shared__ float rsm[8 * HIDD];
    int tid = threadIdx.x;
    int blockRow = blockIdx.x * 128;
    if (tid < HIDD) {
        sa[tid] = g_a[tid]; sc[tid] = g_c[tid];
        int grow = blockRow + tid;
        sdv[tid] = (grow < Nn) ? g_dinv[grow] : 0.f;
    }
    __syncthreads();
    int tx = tid & 15, ty = tid >> 4;
    int ro = ty * 8, co = tx * 8;
    unsigned long long acc[8][4];
    #pragma unroll
    for (int i = 0; i < 8; i++)
        #pragma unroll
        for (int j = 0; j < 4; j++) acc[i][j] = 0ull;
    float rp0 = 0.f, rp1 = 0.f, rp2 = 0.f, rp3 = 0.f;
    for (int kc = 0; kc < 128; kc += GBK) {
        #pragma unroll
        for (int i = 0; i < 4; i++) {
            int v = tid + i * 256;       // [0,1024)
            int row = v >> 3, kq = v & 7;
            int grow = blockRow + row;
            float4 val = make_float4(0.f, 0.f, 0.f, 0.f);
            if (grow < Nn) val = *(const float4*)&g_act[grow * 128 + kc + kq * 4];
            Ast[(kq * 4 + 0) * 132 + row] = val.x;
            Ast[(kq * 4 + 1) * 132 + row] = val.y;
            Ast[(kq * 4 + 2) * 132 + row] = val.z;
            Ast[(kq * 4 + 3) * 132 + row] = val.w;
        }
        #pragma unroll
        for (int i = 0; i < 4; i++) {
            int v = tid + i * 256;
            int kk = v >> 5, jq = v & 31;
            int k = kc + kk;
            float4 w = *(const float4*)&W[k * 128 + jq * 4];
            float ak = sa[k], ck = sc[k];
            rp0 = fmaf(ck, w.x, rp0); rp1 = fmaf(ck, w.y, rp1);
            rp2 = fmaf(ck, w.z, rp2); rp3 = fmaf(ck, w.w, rp3);
            w.x *= ak; w.y *= ak; w.z *= ak; w.w *= ak;
            *(float4*)&Ws[kk * 128 + jq * 4] = w;
        }
        __syncthreads();
        #pragma unroll
        for (int kk = 0; kk < GBK; kk++) {
            float a[8];
            *(float4*)(a)     = *(float4*)&Ast[kk * 132 + ro];
            *(float4*)(a + 4) = *(float4*)&Ast[kk * 132 + ro + 4];
            ulonglong2 b01 = *(ulonglong2*)&Ws[kk * 128 + co];
            ulonglong2 b23 = *(ulonglong2*)&Ws[kk * 128 + co + 4];
            unsigned long long bp0 = b01.x, bp1 = b01.y, bp2 = b23.x, bp3 = b23.y;
            #pragma unroll
            for (int i2 = 0; i2 < 8; i2++) {
                unsigned long long ap = pack2_dup(a[i2]);
                ffma2(acc[i2][0], ap, bp0);
                ffma2(acc[i2][1], ap, bp1);
                ffma2(acc[i2][2], ap, bp2);
                ffma2(acc[i2][3], ap, bp3);
            }
        }
        __syncthreads();
    }
    // reduce r across the 8 k-groups (jq = tid&31 fixed per thread)
    *(float4*)&rsm[(tid >> 5) * HIDD + (tid & 31) * 4] = make_float4(rp0, rp1, rp2, rp3);
    __syncthreads();
    if (tid < HIDD) {
        float s = 0.f;
        #pragma unroll
        for (int w = 0; w < 8; w++) s += rsm[w * HIDD + tid];
        Ws[tid] = s; // reuse Ws front as rfin
    }
    __syncthreads();
    float rl[8];
    *(float4*)(rl)     = *(float4*)&Ws[co];
    *(float4*)(rl + 4) = *(float4*)&Ws[co + 4];
    #pragma unroll
    for (int i2 = 0; i2 < 8; i2++) {
        int grow = blockRow + ro + i2;
        if (grow < Nn) {
            float dvr = sdv[ro + i2];
            float2 p0 = ull2f2(acc[i2][0]), p1 = ull2f2(acc[i2][1]);
            float2 p2 = ull2f2(acc[i2][2]), p3 = ull2f2(acc[i2][3]);
            *(float4*)&g_h[grow * 128 + co] =
                make_float4(dvr * (p0.x + rl[0]), dvr * (p0.y + rl[1]),
                            dvr * (p1.x + rl[2]), dvr * (p1.y + rl[3]));
            *(float4*)&g_h[grow * 128 + co + 4] =
                make_float4(dvr * (p2.x + rl[4]), dvr * (p2.y + rl[5]),
                            dvr * (p3.x + rl[6]), dvr * (p3.y + rl[7]));
        }
    }
}

// ------- aggregation + bias + rational + fused BN stats (banked fp64 atomics) ------
// 8 warps per block, one node per warp. Gather in unrolled groups of 8 independent
// float4 adds (MLP=8); padded lanes index the zero row (Nn) so they add 0.
// h rows are pre-scaled by dinv[src]; final result scaled by dinv[dst].
__global__ __launch_bounds__(256) void agg_kernel(const float* __restrict__ bvec,
                           const float* __restrict__ rat_num,
                           const float* __restrict__ rat_den,
                           const int* __restrict__ assign) {
    __shared__ float s_num[CLUST * 6];
    __shared__ float s_den[CLUST * 4];
    __shared__ int   s_as[HIDD];
    __shared__ float s_b[HIDD];
    __shared__ float sp_sum[8 * HIDD];
    __shared__ float sp_sq[8 * HIDD];
    int tid = threadIdx.x;
    if (tid < CLUST * 6) s_num[tid] = rat_num[tid];
    if (tid < CLUST * 4) s_den[tid] = rat_den[tid];
    if (tid < HIDD) { s_as[tid] = assign[tid]; s_b[tid] = bvec[tid]; }
    __syncthreads();
    int lane = tid & 31;
    int wid = tid >> 5;
    int v = blockIdx.x * 8 + wid;
    float dv = g_dinv[v];
    int beg = g_rowptr[v], end = g_rowptr[v + 1];
    float4 acc = make_float4(0.f, 0.f, 0.f, 0.f);
    const unsigned FULL = 0xffffffffu;
    for (int base = beg; base < end; base += 32) {
        int my = (base + lane < end) ? g_csr[base + lane] : Nn;
        int m = min(32, end - base);
        for (int k = 0; k < m; k += 8) {
            int si[8];
            #pragma unroll
            for (int i = 0; i < 8; i++) si[i] = __shfl_sync(FULL, my, k + i);
            float4 hv[8];
            #pragma unroll
            for (int i = 0; i < 8; i++)
                hv[i] = *(const float4*)&g_h[si[i] * 128 + lane * 4];
            #pragma unroll
            for (int i = 0; i < 8; i++) {
                acc.x += hv[i].x;
                acc.y += hv[i].y;
                acc.z += hv[i].z;
                acc.w += hv[i].w;
            }
        }
    }
    {   // self term: + h'_v, then scale by dinv_v and add bias
        float4 hs = *(const float4*)&g_h[v * 128 + lane * 4];
        float4 bb = *(const float4*)&s_b[lane * 4];
        acc.x = fmaf(dv, acc.x + hs.x, bb.x);
        acc.y = fmaf(dv, acc.y + hs.y, bb.y);
        acc.z = fmaf(dv, acc.z + hs.z, bb.z);
        acc.w = fmaf(dv, acc.w + hs.w, bb.w);
    }
    float z[4] = {acc.x, acc.y, acc.z, acc.w};
    float out[4];
    #pragma unroll
    for (int c = 0; c < 4; c++) {
        int j = lane * 4 + c;
        int cl = s_as[j];
        const float* a = &s_num[cl * 6];
        const float* q = &s_den[cl * 4];
        float xx = z[c];
        float P = a[5];
        P = fmaf(P, xx, a[4]); P = fmaf(P, xx, a[3]); P = fmaf(P, xx, a[2]);
        P = fmaf(P, xx, a[1]); P = fmaf(P, xx, a[0]);
        float Q = q[3];
        Q = fmaf(Q, xx, q[2]); Q = fmaf(Q, xx, q[1]); Q = fmaf(Q, xx, q[0]);
        Q *= xx;
        out[c] = P / (1.0f + fabsf(Q));
        sp_sum[wid * HIDD + j] = out[c];
        sp_sq[wid * HIDD + j]  = out[c] * out[c];
    }
    *(float4*)&g_act[v * 128 + lane * 4] = make_float4(out[0], out[1], out[2], out[3]);
    __syncthreads();
    if (tid < HIDD) {
        float s = 0.f, q = 0.f;
        #pragma unroll
        for (int w = 0; w < 8; w++) {
            s += sp_sum[w * HIDD + tid];
            q += sp_sq[w * HIDD + tid];
        }
        int bank = (blockIdx.x & (SBANK - 1)) * HIDD;
        atomicAdd(&g_sum[bank + tid], (double)s);
        atomicAdd(&g_sq[bank + tid], (double)q);
    }
}

// ---- stats -> BN affine (a, c); sums banks; resets stats ----
__global__ void s2a_kernel(const float* __restrict__ gw, const float* __restrict__ be) {
    int j = threadIdx.x;
    double su = 0.0, sq = 0.0;
    #pragma unroll
    for (int b = 0; b < SBANK; b++) {
        su += g_sum[b * HIDD + j];
        sq += g_sq[b * HIDD + j];
        g_sum[b * HIDD + j] = 0.0;
        g_sq[b * HIDD + j] = 0.0;
    }
    double mean = su * (1.0 / (double)Nn);
    double var = sq * (1.0 / (double)Nn) - mean * mean;
    float a = gw[j] * rsqrtf((float)var + EPSv);
    g_a[j] = a;
    g_c[j] = be[j] - (float)mean * a;
}

// ---------------- pooling (4 accumulators x 2 row-groups, BN affine applied) -------
__global__ void pool_kernel(const int* __restrict__ batch) {
    __shared__ int s_se[2];
    __shared__ float part[256];
    int tid = threadIdx.x; // 256
    int g = blockIdx.x;
    if (tid < 2) {
        int target = g + tid;
        int lo = 0, hi = Nn;
        while (lo < hi) { int mid = (lo + hi) >> 1; if (batch[mid] < target) lo = mid + 1; else hi = mid; }
        s_se[tid] = lo;
    }
    __syncthreads();
    int s = s_se[0], e = s_se[1];
    int j = tid & 127, half = tid >> 7;
    float a0 = 0.f, a1 = 0.f, a2 = 0.f, a3 = 0.f;
    int n = s + half;
    for (; n + 6 < e; n += 8) {
        a0 += g_act[n * 128 + j];
        a1 += g_act[(n + 2) * 128 + j];
        a2 += g_act[(n + 4) * 128 + j];
        a3 += g_act[(n + 6) * 128 + j];
    }
    for (; n < e; n += 2) a0 += g_act[n * 128 + j];
    part[tid] = (a0 + a1) + (a2 + a3);
    __syncthreads();
    if (tid < 128) {
        float m = part[tid] + part[tid + 128];
        float out = 0.f;
        if (e > s) out = fmaf(g_a[tid], m / (float)(e - s), g_c[tid]);
        g_pooled[g * 128 + tid] = out;
    }
}

// ---------------- MLP head (4 independent FMA chains) ----------------
__global__ void mlp_kernel(const float* __restrict__ W, const float* __restrict__ bias, int stage) {
    __shared__ float srow[128];
    int g = blockIdx.x, j = threadIdx.x;
    const float* in = (stage == 1) ? g_pooled : g_z1;
    float* out = (stage == 1) ? g_z1 : g_z2;
    srow[j] = in[g * 128 + j];
    __syncthreads();
    float s0 = bias[j], s1 = 0.f, s2 = 0.f, s3 = 0.f;
    #pragma unroll
    for (int k = 0; k < 128; k += 4) {
        s0 = fmaf(srow[k],     W[(k)     * 128 + j], s0);
        s1 = fmaf(srow[k + 1], W[(k + 1) * 128 + j], s1);
        s2 = fmaf(srow[k + 2], W[(k + 2) * 128 + j], s2);
        s3 = fmaf(srow[k + 3], W[(k + 3) * 128 + j], s3);
    }
    float s = (s0 + s1) + (s2 + s3);
    s = 0.5f * s * (1.0f + erff(s * 0.70710678118654752f));
    out[g * 128 + j] = s;
}

__global__ void mlp3_kernel(const float* __restrict__ W, const float* __restrict__ bias,
                            float* __restrict__ out) {
    __shared__ float srow[128];
    int g = blockIdx.x, j = threadIdx.x;
    srow[j] = g_z2[g * 128 + j];
    __syncthreads();
    if (j < OUTD) {
        float s0 = bias[j], s1 = 0.f, s2 = 0.f, s3 = 0.f;
        #pragma unroll
        for (int k = 0; k < 128; k += 4) {
            s0 = fmaf(srow[k],     W[(k)     * OUTD + j], s0);
            s1 = fmaf(srow[k + 1], W[(k + 1) * OUTD + j], s1);
            s2 = fmaf(srow[k + 2], W[(k + 2) * OUTD + j], s2);
            s3 = fmaf(srow[k + 3], W[(k + 3) * OUTD + j], s3);
        }
        out[g * OUTD + j] = (s0 + s1) + (s2 + s3);
    }
}

// ---------------- host launch ----------------
extern "C" void kernel_launch(void* const* d_in, const int* in_sizes, int n_in,
                              void* d_out, int out_size) {
    (void)in_sizes; (void)n_in; (void)out_size;
    const float* x       = (const float*)d_in[0];
    const int*   ei      = (const int*)d_in[1];
    const int*   batch   = (const int*)d_in[2];
    const float* W[4]    = {(const float*)d_in[3],  (const float*)d_in[7],
                            (const float*)d_in[11], (const float*)d_in[15]};
    const float* bv[4]   = {(const float*)d_in[4],  (const float*)d_in[8],
                            (const float*)d_in[12], (const float*)d_in[16]};
    const float* gv[4]   = {(const float*)d_in[5],  (const float*)d_in[9],
                            (const float*)d_in[13], (const float*)d_in[17]};
    const float* bev[4]  = {(const float*)d_in[6],  (const float*)d_in[10],
                            (const float*)d_in[14], (const float*)d_in[18]};
    const float* rat_num = (const float*)d_in[19];
    const float* rat_den = (const float*)d_in[20];
    const int*   assign  = (const int*)d_in[21];
    const float* HW1     = (const float*)d_in[22];
    const float* Hb1     = (const float*)d_in[23];
    const float* HW2     = (const float*)d_in[24];
    const float* Hb2     = (const float*)d_in[25];
    const float* HW3     = (const float*)d_in[26];
    const float* Hb3     = (const float*)d_in[27];
    float* out = (float*)d_out;

    const int TB = 256;
    const int nBlocksN = (Nn + TB - 1) / TB;         // 196
    const int nBlocksE = (Ee + TB - 1) / TB;         // 3125
    const int nBlocksAgg = Nn / 8;                   // 6250 (exact)
    const int nBlocksGemm = (Nn + 127) / 128;        // 391

    // ---- graph structure (per launch; deterministic) ----
    init_kernel<<<nBlocksN, TB>>>();
    hist_kernel<<<nBlocksE, TB>>>(ei);
    bsum_kernel<<<NB, 128>>>();
    bscan_kernel<<<1, 512>>>();
    rowptr_kernel<<<NB, 128>>>();                     // + dinv
    fill_kernel<<<nBlocksE, TB>>>(ei);                // atomic-free placement

    // ---- layer 0 ----
    gemm0_kernel<<<1024, TB>>>(x, W[0]);
    agg_kernel<<<nBlocksAgg, TB>>>(bv[0], rat_num, rat_den, assign);

    // ---- layers 1..3 (BN folded into GEMM: a-scale on W load, +r, x dinv) ----
    for (int i = 1; i < 4; i++) {
        s2a_kernel<<<1, 128>>>(gv[i - 1], bev[i - 1]);
        gemm_kernel<<<nBlocksGemm, 256>>>(W[i]);
        agg_kernel<<<nBlocksAgg, TB>>>(bv[i], rat_num, rat_den, assign);
    }

    // ---- final BN affine + pooling + MLP head ----
    s2a_kernel<<<1, 128>>>(gv[3], bev[3]);
    pool_kernel<<<Gg, 256>>>(batch);
    mlp_kernel<<<Gg, 128>>>(HW1, Hb1, 1);
    mlp_kernel<<<Gg, 128>>>(HW2, Hb2, 2);
    mlp3_kernel<<<Gg, 128>>>(HW3, Hb3, out);
}

// round 15
// speedup vs baseline: 1.0311x; 1.0311x over previous
#include <cuda_runtime.h>
#include <math.h>

// Problem constants
#define Nn 50000
#define Ee 800000
#define IND 9
#define HIDD 128
#define Gg 256
#define OUTD 10
#define CLUST 20
#define EPSv 1e-5f
#define SBANK 8
#define NB 392   // ceil(Nn/128)
#define FILLB 3125
#define G0B 1024

// ---------------- scratch (device globals; no allocation allowed) ----------------
// g_h: fp32, pre-scaled by dinv[row]; row Nn is a zero pad row (never written,
// device globals are zero-initialized at module load).
__device__ float  g_h[(Nn + 1) * HIDD];
__device__ float  g_act[Nn * HIDD];      // rational output (pre-BN), fp32
__device__ int    g_cnt[Nn];             // self-restored to 0 by rowptr_kernel
__device__ int    g_rank[Ee];
__device__ int    g_rowptr[Nn + 1];
__device__ int    g_csr[Ee];             // per dst-sorted edge: src only
__device__ float  g_dinv[Nn];
__device__ int    g_bsum[NB];
// per-layer banked BN stats; zero-restored by mlpfused_kernel each run
__device__ double g_sumL[4 * SBANK * HIDD];
__device__ double g_sqL[4 * SBANK * HIDD];
__device__ float  g_pooled[Gg * HIDD];

// ---------------- f32x2 packed-FMA helpers ----------------
__device__ __forceinline__ unsigned long long pack2_dup(float x) {
    unsigned long long r;
    asm("mov.b64 %0, {%1, %1};" : "=l"(r) : "f"(x));
    return r;
}
__device__ __forceinline__ void ffma2(unsigned long long& d, unsigned long long a,
                                      unsigned long long b) {
    asm("fma.rn.f32x2 %0, %1, %2, %0;" : "+l"(d) : "l"(a), "l"(b));
}
__device__ __forceinline__ float2 ull2f2(unsigned long long u) {
    float2 f;
    asm("mov.b64 {%0, %1}, %2;" : "=f"(f.x), "=f"(f.y) : "l"(u));
    return f;
}

// ---------------- structure build ----------------
__global__ void hist_kernel(const int* __restrict__ ei) {
    int e = blockIdx.x * blockDim.x + threadIdx.x;
    if (e < Ee) g_rank[e] = atomicAdd(&g_cnt[ei[Ee + e]], 1);
}

// per-128-chunk sums
__global__ void bsum_kernel() {
    int idx = blockIdx.x * 128 + threadIdx.x;
    int c = (idx < Nn) ? g_cnt[idx] : 0;
    #pragma unroll
    for (int o = 16; o; o >>= 1) c += __shfl_xor_sync(0xffffffffu, c, o);
    __shared__ int ws[4];
    if ((threadIdx.x & 31) == 0) ws[threadIdx.x >> 5] = c;
    __syncthreads();
    if (threadIdx.x == 0) g_bsum[blockIdx.x] = ws[0] + ws[1] + ws[2] + ws[3];
}

// rowptr: inline prefix over block sums + local scan; also dinv; restores cnt=0
__global__ void rowptr_kernel() {
    __shared__ int ws[4];
    __shared__ int s_boff;
    int t = threadIdx.x;
    int lane = t & 31, w = t >> 5;
    // exclusive prefix of g_bsum up to blockIdx.x
    int part = 0;
    for (int i = t; i < NB; i += 128) part += (i < (int)blockIdx.x) ? g_bsum[i] : 0;
    #pragma unroll
    for (int o = 16; o; o >>= 1) part += __shfl_xor_sync(0xffffffffu, part, o);
    if (lane == 0) ws[w] = part;
    __syncthreads();
    if (t == 0) s_boff = ws[0] + ws[1] + ws[2] + ws[3];
    __syncthreads();
    int idx = blockIdx.x * 128 + t;
    int c = (idx < Nn) ? g_cnt[idx] : 0;
    int inc = c;
    #pragma unroll
    for (int o = 1; o < 32; o <<= 1) {
        int u = __shfl_up_sync(0xffffffffu, inc, o);
        if (lane >= o) inc += u;
    }
    __syncthreads();
    if (lane == 31) ws[w] = inc;
    __syncthreads();
    int wo = 0;
    #pragma unroll
    for (int i = 0; i < 4; i++) wo += (i < w) ? ws[i] : 0;
    int excl = s_boff + wo + inc - c;
    if (idx < Nn) {
        g_rowptr[idx] = excl;
        g_dinv[idx] = rsqrtf((float)c + 1.0f);
        g_cnt[idx] = 0;  // restore invariant for next run
    }
    if (blockIdx.x == 0 && t == 0) g_rowptr[Nn] = Ee;
}

// ---- combined: CSR fill (blocks [0,FILLB)) + layer-0 GEMM (blocks [FILLB,+G0B)) ----
__global__ void fill_gemm0_kernel(const int* __restrict__ ei,
                                  const float* __restrict__ x,
                                  const float* __restrict__ W0) {
    __shared__ float sW[IND * HIDD];
    int tid = threadIdx.x;
    if (blockIdx.x < FILLB) {
        int e = blockIdx.x * 256 + tid;
        if (e < Ee) {
            int d = ei[Ee + e];
            g_csr[g_rowptr[d] + g_rank[e]] = ei[e];
        }
    } else {
        int vb = blockIdx.x - FILLB;
        for (int i = tid; i < IND * HIDD; i += 256) sW[i] = W0[i];
        __syncthreads();
        int j = tid & 127;
        int r0 = vb * 2 + (tid >> 7);
        for (int n = r0; n < Nn; n += G0B * 2) {
            float acc = 0.f;
            #pragma unroll
            for (int k = 0; k < IND; k++) acc = fmaf(x[n * IND + k], sW[k * HIDD + j], acc);
            g_h[n * HIDD + j] = acc * g_dinv[n];
        }
    }
}

// ---- SGEMM (f32x2): g_h = dinv_row * ((act * a_row) @ W + r),  r = c @ W ----
// BN (a,c) of previous layer computed inline from banked fp64 stats.
#define GBK 32
__global__ __launch_bounds__(256, 2) void gemm_kernel(const float* __restrict__ W,
                                                      const float* __restrict__ gw,
                                                      const float* __restrict__ be,
                                                      int prevLayer) {
    __shared__ float Ast[GBK * 132]; // transposed A chunk [k][row], pad 132
    __shared__ float Ws[GBK * 128];  // B chunk [k][j], pre-scaled by a[k]
    __shared__ float sa[HIDD], sc[HIDD], sdv[HIDD];
    __shared__ float rsm[8 * HIDD];
    int tid = threadIdx.x;
    int blockRow = blockIdx.x * 128;
    if (tid < HIDD) {
        const double* bs = g_sumL + prevLayer * SBANK * HIDD;
        const double* bq = g_sqL + prevLayer * SBANK * HIDD;
        double su = 0.0, sq = 0.0;
        #pragma unroll
        for (int b = 0; b < SBANK; b++) {
            su += bs[b * HIDD + tid];
            sq += bq[b * HIDD + tid];
        }
        double mean = su * (1.0 / (double)Nn);
        double var = sq * (1.0 / (double)Nn) - mean * mean;
        float a = gw[tid] * rsqrtf((float)var + EPSv);
        sa[tid] = a;
        sc[tid] = be[tid] - (float)mean * a;
        int grow = blockRow + tid;
        sdv[tid] = (grow < Nn) ? g_dinv[grow] : 0.f;
    }
    __syncthreads();
    int tx = tid & 15, ty = tid >> 4;
    int ro = ty * 8, co = tx * 8;
    unsigned long long acc[8][4];
    #pragma unroll
    for (int i = 0; i < 8; i++)
        #pragma unroll
        for (int j = 0; j < 4; j++) acc[i][j] = 0ull;
    float rp0 = 0.f, rp1 = 0.f, rp2 = 0.f, rp3 = 0.f;
    for (int kc = 0; kc < 128; kc += GBK) {
        #pragma unroll
        for (int i = 0; i < 4; i++) {
            int v = tid + i * 256;       // [0,1024)
            int row = v >> 3, kq = v & 7;
            int grow = blockRow + row;
            float4 val = make_float4(0.f, 0.f, 0.f, 0.f);
            if (grow < Nn) val = *(const float4*)&g_act[grow * 128 + kc + kq * 4];
            Ast[(kq * 4 + 0) * 132 + row] = val.x;
            Ast[(kq * 4 + 1) * 132 + row] = val.y;
            Ast[(kq * 4 + 2) * 132 + row] = val.z;
            Ast[(kq * 4 + 3) * 132 + row] = val.w;
        }
        #pragma unroll
        for (int i = 0; i < 4; i++) {
            int v = tid + i * 256;
            int kk = v >> 5, jq = v & 31;
            int k = kc + kk;
            float4 w = *(const float4*)&W[k * 128 + jq * 4];
            float ak = sa[k], ck = sc[k];
            rp0 = fmaf(ck, w.x, rp0); rp1 = fmaf(ck, w.y, rp1);
            rp2 = fmaf(ck, w.z, rp2); rp3 = fmaf(ck, w.w, rp3);
            w.x *= ak; w.y *= ak; w.z *= ak; w.w *= ak;
            *(float4*)&Ws[kk * 128 + jq * 4] = w;
        }
        __syncthreads();
        #pragma unroll
        for (int kk = 0; kk < GBK; kk++) {
            float a[8];
            *(float4*)(a)     = *(float4*)&Ast[kk * 132 + ro];
            *(float4*)(a + 4) = *(float4*)&Ast[kk * 132 + ro + 4];
            ulonglong2 b01 = *(ulonglong2*)&Ws[kk * 128 + co];
            ulonglong2 b23 = *(ulonglong2*)&Ws[kk * 128 + co + 4];
            unsigned long long bp0 = b01.x, bp1 = b01.y, bp2 = b23.x, bp3 = b23.y;
            #pragma unroll
            for (int i2 = 0; i2 < 8; i2++) {
                unsigned long long ap = pack2_dup(a[i2]);
                ffma2(acc[i2][0], ap, bp0);
                ffma2(acc[i2][1], ap, bp1);
                ffma2(acc[i2][2], ap, bp2);
                ffma2(acc[i2][3], ap, bp3);
            }
        }
        __syncthreads();
    }
    // reduce r across the 8 k-groups (jq = tid&31 fixed per thread)
    *(float4*)&rsm[(tid >> 5) * HIDD + (tid & 31) * 4] = make_float4(rp0, rp1, rp2, rp3);
    __syncthreads();
    if (tid < HIDD) {
        float s = 0.f;
        #pragma unroll
        for (int w = 0; w < 8; w++) s += rsm[w * HIDD + tid];
        Ws[tid] = s; // reuse Ws front as rfin
    }
    __syncthreads();
    float rl[8];
    *(float4*)(rl)     = *(float4*)&Ws[co];
    *(float4*)(rl + 4) = *(float4*)&Ws[co + 4];
    #pragma unroll
    for (int i2 = 0; i2 < 8; i2++) {
        int grow = blockRow + ro + i2;
        if (grow < Nn) {
            float dvr = sdv[ro + i2];
            float2 p0 = ull2f2(acc[i2][0]), p1 = ull2f2(acc[i2][1]);
            float2 p2 = ull2f2(acc[i2][2]), p3 = ull2f2(acc[i2][3]);
            *(float4*)&g_h[grow * 128 + co] =
                make_float4(dvr * (p0.x + rl[0]), dvr * (p0.y + rl[1]),
                            dvr * (p1.x + rl[2]), dvr * (p1.y + rl[3]));
            *(float4*)&g_h[grow * 128 + co + 4] =
                make_float4(dvr * (p2.x + rl[4]), dvr * (p2.y + rl[5]),
                            dvr * (p3.x + rl[6]), dvr * (p3.y + rl[7]));
        }
    }
}

// ------- aggregation + bias + rational + fused BN stats (banked fp64 atomics) ------
// 8 warps per block, one node per warp. Gather in unrolled groups of 8 independent
// float4 loads (MLP=8); padded lanes index the zero row (Nn) so they add 0.
// h rows are pre-scaled by dinv[src]; final result scaled by dinv[dst].
__global__ __launch_bounds__(256) void agg_kernel(const float* __restrict__ bvec,
                           const float* __restrict__ rat_num,
                           const float* __restrict__ rat_den,
                           const int* __restrict__ assign,
                           int layer) {
    __shared__ float s_num[CLUST * 6];
    __shared__ float s_den[CLUST * 4];
    __shared__ int   s_as[HIDD];
    __shared__ float s_b[HIDD];
    __shared__ float sp_sum[8 * HIDD];
    __shared__ float sp_sq[8 * HIDD];
    int tid = threadIdx.x;
    if (tid < CLUST * 6) s_num[tid] = rat_num[tid];
    if (tid < CLUST * 4) s_den[tid] = rat_den[tid];
    if (tid < HIDD) { s_as[tid] = assign[tid]; s_b[tid] = bvec[tid]; }
    __syncthreads();
    int lane = tid & 31;
    int wid = tid >> 5;
    int v = blockIdx.x * 8 + wid;
    float dv = g_dinv[v];
    int beg = g_rowptr[v], end = g_rowptr[v + 1];
    float4 acc = make_float4(0.f, 0.f, 0.f, 0.f);
    const unsigned FULL = 0xffffffffu;
    for (int base = beg; base < end; base += 32) {
        int my = (base + lane < end) ? g_csr[base + lane] : Nn;
        int m = min(32, end - base);
        for (int k = 0; k < m; k += 8) {
            int si[8];
            #pragma unroll
            for (int i = 0; i < 8; i++) si[i] = __shfl_sync(FULL, my, k + i);
            float4 hv[8];
            #pragma unroll
            for (int i = 0; i < 8; i++)
                hv[i] = *(const float4*)&g_h[si[i] * 128 + lane * 4];
            #pragma unroll
            for (int i = 0; i < 8; i++) {
                acc.x += hv[i].x;
                acc.y += hv[i].y;
                acc.z += hv[i].z;
                acc.w += hv[i].w;
            }
        }
    }
    {   // self term: + h'_v, then scale by dinv_v and add bias
        float4 hs = *(const float4*)&g_h[v * 128 + lane * 4];
        float4 bb = *(const float4*)&s_b[lane * 4];
        acc.x = fmaf(dv, acc.x + hs.x, bb.x);
        acc.y = fmaf(dv, acc.y + hs.y, bb.y);
        acc.z = fmaf(dv, acc.z + hs.z, bb.z);
        acc.w = fmaf(dv, acc.w + hs.w, bb.w);
    }
    float z[4] = {acc.x, acc.y, acc.z, acc.w};
    float out[4];
    #pragma unroll
    for (int c = 0; c < 4; c++) {
        int j = lane * 4 + c;
        int cl = s_as[j];
        const float* a = &s_num[cl * 6];
        const float* q = &s_den[cl * 4];
        float xx = z[c];
        float P = a[5];
        P = fmaf(P, xx, a[4]); P = fmaf(P, xx, a[3]); P = fmaf(P, xx, a[2]);
        P = fmaf(P, xx, a[1]); P = fmaf(P, xx, a[0]);
        float Q = q[3];
        Q = fmaf(Q, xx, q[2]); Q = fmaf(Q, xx, q[1]); Q = fmaf(Q, xx, q[0]);
        Q *= xx;
        out[c] = P / (1.0f + fabsf(Q));
        sp_sum[wid * HIDD + j] = out[c];
        sp_sq[wid * HIDD + j]  = out[c] * out[c];
    }
    *(float4*)&g_act[v * 128 + lane * 4] = make_float4(out[0], out[1], out[2], out[3]);
    __syncthreads();
    if (tid < HIDD) {
        float s = 0.f, q = 0.f;
        #pragma unroll
        for (int w = 0; w < 8; w++) {
            s += sp_sum[w * HIDD + tid];
            q += sp_sq[w * HIDD + tid];
        }
        int bank = layer * SBANK * HIDD + (blockIdx.x & (SBANK - 1)) * HIDD;
        atomicAdd(&g_sumL[bank + tid], (double)s);
        atomicAdd(&g_sqL[bank + tid], (double)q);
    }
}

// ---------------- pooling (inline layer-3 BN affine from banks) ----------------
__global__ void pool_kernel(const int* __restrict__ batch,
                            const float* __restrict__ gw,
                            const float* __restrict__ be) {
    __shared__ int s_se[2];
    __shared__ float part[256];
    __shared__ float sa[HIDD], sc[HIDD];
    int tid = threadIdx.x; // 256
    int g = blockIdx.x;
    if (tid < 2) {
        int target = g + tid;
        int lo = 0, hi = Nn;
        while (lo < hi) { int mid = (lo + hi) >> 1; if (batch[mid] < target) lo = mid + 1; else hi = mid; }
        s_se[tid] = lo;
    }
    if (tid < HIDD) {
        const double* bs = g_sumL + 3 * SBANK * HIDD;
        const double* bq = g_sqL + 3 * SBANK * HIDD;
        double su = 0.0, sq = 0.0;
        #pragma unroll
        for (int b = 0; b < SBANK; b++) {
            su += bs[b * HIDD + tid];
            sq += bq[b * HIDD + tid];
        }
        double mean = su * (1.0 / (double)Nn);
        double var = sq * (1.0 / (double)Nn) - mean * mean;
        float a = gw[tid] * rsqrtf((float)var + EPSv);
        sa[tid] = a;
        sc[tid] = be[tid] - (float)mean * a;
    }
    __syncthreads();
    int s = s_se[0], e = s_se[1];
    int j = tid & 127, half = tid >> 7;
    float a0 = 0.f, a1 = 0.f, a2 = 0.f, a3 = 0.f;
    int n = s + half;
    for (; n + 6 < e; n += 8) {
        a0 += g_act[n * 128 + j];
        a1 += g_act[(n + 2) * 128 + j];
        a2 += g_act[(n + 4) * 128 + j];
        a3 += g_act[(n + 6) * 128 + j];
    }
    for (; n < e; n += 2) a0 += g_act[n * 128 + j];
    part[tid] = (a0 + a1) + (a2 + a3);
    __syncthreads();
    if (tid < 128) {
        float m = part[tid] + part[tid + 128];
        float out = 0.f;
        if (e > s) out = fmaf(sa[tid], m / (float)(e - s), sc[tid]);
        g_pooled[g * 128 + tid] = out;
    }
}

// ---------------- fused MLP head (3 stages, one block per graph) ----------------
// Also zero-restores the per-layer stat banks for the next run.
__global__ void mlpfused_kernel(const float* __restrict__ HW1, const float* __restrict__ Hb1,
                                const float* __restrict__ HW2, const float* __restrict__ Hb2,
                                const float* __restrict__ HW3, const float* __restrict__ Hb3,
                                float* __restrict__ out) {
    __shared__ float srow[128], srow2[128];
    int g = blockIdx.x, j = threadIdx.x;
    srow[j] = g_pooled[g * 128 + j];
    if (j < 16) {   // zero 16 doubles per array per block: 256*16 = 4096 total
        g_sumL[g * 16 + j] = 0.0;
        g_sqL[g * 16 + j] = 0.0;
    }
    __syncthreads();
    {
        float s0 = Hb1[j], s1 = 0.f, s2 = 0.f, s3 = 0.f;
        #pragma unroll
        for (int k = 0; k < 128; k += 4) {
            s0 = fmaf(srow[k],     HW1[(k)     * 128 + j], s0);
            s1 = fmaf(srow[k + 1], HW1[(k + 1) * 128 + j], s1);
            s2 = fmaf(srow[k + 2], HW1[(k + 2) * 128 + j], s2);
            s3 = fmaf(srow[k + 3], HW1[(k + 3) * 128 + j], s3);
        }
        float s = (s0 + s1) + (s2 + s3);
        srow2[j] = 0.5f * s * (1.0f + erff(s * 0.70710678118654752f));
    }
    __syncthreads();
    {
        float s0 = Hb2[j], s1 = 0.f, s2 = 0.f, s3 = 0.f;
        #pragma unroll
        for (int k = 0; k < 128; k += 4) {
            s0 = fmaf(srow2[k],     HW2[(k)     * 128 + j], s0);
            s1 = fmaf(srow2[k + 1], HW2[(k + 1) * 128 + j], s1);
            s2 = fmaf(srow2[k + 2], HW2[(k + 2) * 128 + j], s2);
            s3 = fmaf(srow2[k + 3], HW2[(k + 3) * 128 + j], s3);
        }
        float s = (s0 + s1) + (s2 + s3);
        srow[j] = 0.5f * s * (1.0f + erff(s * 0.70710678118654752f));
    }
    __syncthreads();
    if (j < OUTD) {
        float s0 = Hb3[j], s1 = 0.f, s2 = 0.f, s3 = 0.f;
        #pragma unroll
        for (int k = 0; k < 128; k += 4) {
            s0 = fmaf(srow[k],     HW3[(k)     * OUTD + j], s0);
            s1 = fmaf(srow[k + 1], HW3[(k + 1) * OUTD + j], s1);
            s2 = fmaf(srow[k + 2], HW3[(k + 2) * OUTD + j], s2);
            s3 = fmaf(srow[k + 3], HW3[(k + 3) * OUTD + j], s3);
        }
        out[g * OUTD + j] = (s0 + s1) + (s2 + s3);
    }
}

// ---------------- host launch ----------------
extern "C" void kernel_launch(void* const* d_in, const int* in_sizes, int n_in,
                              void* d_out, int out_size) {
    (void)in_sizes; (void)n_in; (void)out_size;
    const float* x       = (const float*)d_in[0];
    const int*   ei      = (const int*)d_in[1];
    const int*   batch   = (const int*)d_in[2];
    const float* W[4]    = {(const float*)d_in[3],  (const float*)d_in[7],
                            (const float*)d_in[11], (const float*)d_in[15]};
    const float* bv[4]   = {(const float*)d_in[4],  (const float*)d_in[8],
                            (const float*)d_in[12], (const float*)d_in[16]};
    const float* gv[4]   = {(const float*)d_in[5],  (const float*)d_in[9],
                            (const float*)d_in[13], (const float*)d_in[17]};
    const float* bev[4]  = {(const float*)d_in[6],  (const float*)d_in[10],
                            (const float*)d_in[14], (const float*)d_in[18]};
    const float* rat_num = (const float*)d_in[19];
    const float* rat_den = (const float*)d_in[20];
    const int*   assign  = (const int*)d_in[21];
    const float* HW1     = (const float*)d_in[22];
    const float* Hb1     = (const float*)d_in[23];
    const float* HW2     = (const float*)d_in[24];
    const float* Hb2     = (const float*)d_in[25];
    const float* HW3     = (const float*)d_in[26];
    const float* Hb3     = (const float*)d_in[27];
    float* out = (float*)d_out;

    const int TB = 256;
    const int nBlocksAgg = Nn / 8;                   // 6250 (exact)
    const int nBlocksGemm = (Nn + 127) / 128;        // 391

    // ---- graph structure (per launch; state self-restoring across runs) ----
    hist_kernel<<<FILLB, TB>>>(ei);
    bsum_kernel<<<NB, 128>>>();
    rowptr_kernel<<<NB, 128>>>();                     // + inline bscan + dinv + cnt reset
    fill_gemm0_kernel<<<FILLB + G0B, TB>>>(ei, x, W[0]);

    // ---- layer 0 ----
    agg_kernel<<<nBlocksAgg, TB>>>(bv[0], rat_num, rat_den, assign, 0);

    // ---- layers 1..3 (BN folded into GEMM: inline (a,c), a-scale, +r, x dinv) ----
    for (int i = 1; i < 4; i++) {
        gemm_kernel<<<nBlocksGemm, 256>>>(W[i], gv[i - 1], bev[i - 1], i - 1);
        agg_kernel<<<nBlocksAgg, TB>>>(bv[i], rat_num, rat_den, assign, i);
    }

    // ---- pooling (inline layer-3 BN) + fused MLP head (+ stats bank reset) ----
    pool_kernel<<<Gg, 256>>>(batch, gv[3], bev[3]);
    mlpfused_kernel<<<Gg, 128>>>(HW1, Hb1, HW2, Hb2, HW3, Hb3, out);
}

// round 16
// speedup vs baseline: 1.0569x; 1.0250x over previous
#include <cuda_runtime.h>
#include <math.h>

// Problem constants
#define Nn 50000
#define Ee 800000
#define IND 9
#define HIDD 128
#define Gg 256
#define OUTD 10
#define CLUST 20
#define EPSv 1e-5f
#define SBANK 8
#define NB 392    // ceil(Nn/128)
#define FILLB4 782 // ceil(Ee/1024)
#define G0B 1024

// ---------------- scratch (device globals; no allocation allowed) ----------------
// g_h: fp32, pre-scaled by dinv[row]; row Nn is a zero pad row (never written,
// device globals are zero-initialized at module load).
__device__ float  g_h[(Nn + 1) * HIDD];
__device__ float  g_act[Nn * HIDD];      // rational output (pre-BN), fp32
__device__ int    g_cnt[Nn];             // self-restored to 0 by rowptr_kernel
__device__ int    g_rank[Ee];
__device__ int    g_rowptr[Nn + 1];
__device__ int    g_csr[Ee];             // per dst-sorted edge: src only
__device__ float  g_dinv[Nn];
__device__ int    g_bsum[NB];
// per-layer banked BN stats; zeroed by rowptr_kernel before any agg each call
__device__ double g_sumL[4 * SBANK * HIDD];
__device__ double g_sqL[4 * SBANK * HIDD];

// ---------------- f32x2 packed-FMA helpers ----------------
__device__ __forceinline__ unsigned long long pack2_dup(float x) {
    unsigned long long r;
    asm("mov.b64 %0, {%1, %1};" : "=l"(r) : "f"(x));
    return r;
}
__device__ __forceinline__ void ffma2(unsigned long long& d, unsigned long long a,
                                      unsigned long long b) {
    asm("fma.rn.f32x2 %0, %1, %2, %0;" : "+l"(d) : "l"(a), "l"(b));
}
__device__ __forceinline__ float2 ull2f2(unsigned long long u) {
    float2 f;
    asm("mov.b64 {%0, %1}, %2;" : "=f"(f.x), "=f"(f.y) : "l"(u));
    return f;
}

// ---------------- structure build ----------------
__global__ void hist_kernel(const int* __restrict__ ei) {
    int e = blockIdx.x * blockDim.x + threadIdx.x;
    if (e < Ee) g_rank[e] = atomicAdd(&g_cnt[ei[Ee + e]], 1);
}

// per-128-chunk sums
__global__ void bsum_kernel() {
    int idx = blockIdx.x * 128 + threadIdx.x;
    int c = (idx < Nn) ? g_cnt[idx] : 0;
    #pragma unroll
    for (int o = 16; o; o >>= 1) c += __shfl_xor_sync(0xffffffffu, c, o);
    __shared__ int ws[4];
    if ((threadIdx.x & 31) == 0) ws[threadIdx.x >> 5] = c;
    __syncthreads();
    if (threadIdx.x == 0) g_bsum[blockIdx.x] = ws[0] + ws[1] + ws[2] + ws[3];
}

// rowptr: inline prefix over block sums + local scan; dinv; cnt reset; stats reset
__global__ void rowptr_kernel() {
    __shared__ int ws[4];
    __shared__ int s_boff;
    int t = threadIdx.x;
    int lane = t & 31, w = t >> 5;
    // zero the BN stat banks for this call (runs before any agg)
    {
        int gid = blockIdx.x * 128 + t;
        if (gid < 4 * SBANK * HIDD) { g_sumL[gid] = 0.0; g_sqL[gid] = 0.0; }
    }
    // exclusive prefix of g_bsum up to blockIdx.x
    int part = 0;
    for (int i = t; i < NB; i += 128) part += (i < (int)blockIdx.x) ? g_bsum[i] : 0;
    #pragma unroll
    for (int o = 16; o; o >>= 1) part += __shfl_xor_sync(0xffffffffu, part, o);
    if (lane == 0) ws[w] = part;
    __syncthreads();
    if (t == 0) s_boff = ws[0] + ws[1] + ws[2] + ws[3];
    __syncthreads();
    int idx = blockIdx.x * 128 + t;
    int c = (idx < Nn) ? g_cnt[idx] : 0;
    int inc = c;
    #pragma unroll
    for (int o = 1; o < 32; o <<= 1) {
        int u = __shfl_up_sync(0xffffffffu, inc, o);
        if (lane >= o) inc += u;
    }
    __syncthreads();
    if (lane == 31) ws[w] = inc;
    __syncthreads();
    int wo = 0;
    #pragma unroll
    for (int i = 0; i < 4; i++) wo += (i < w) ? ws[i] : 0;
    int excl = s_boff + wo + inc - c;
    if (idx < Nn) {
        g_rowptr[idx] = excl;
        g_dinv[idx] = rsqrtf((float)c + 1.0f);
        g_cnt[idx] = 0;  // restore invariant for next run
    }
    if (blockIdx.x == 0 && t == 0) g_rowptr[Nn] = Ee;
}

// ---- combined: CSR fill 4 edges/thread (blocks [0,FILLB4)) + layer-0 GEMM ----
__global__ void fill_gemm0_kernel(const int* __restrict__ ei,
                                  const float* __restrict__ x,
                                  const float* __restrict__ W0) {
    __shared__ float sW[IND * HIDD];
    int tid = threadIdx.x;
    if (blockIdx.x < FILLB4) {
        int base = blockIdx.x * 1024 + tid;
        int sv[4], dv[4], rv[4], pv[4];
        bool val[4];
        #pragma unroll
        for (int i = 0; i < 4; i++) {
            int e = base + i * 256;
            val[i] = (e < Ee);
            if (val[i]) {
                sv[i] = ei[e];
                dv[i] = ei[Ee + e];
                rv[i] = g_rank[e];
            }
        }
        #pragma unroll
        for (int i = 0; i < 4; i++) if (val[i]) pv[i] = g_rowptr[dv[i]];
        #pragma unroll
        for (int i = 0; i < 4; i++) if (val[i]) g_csr[pv[i] + rv[i]] = sv[i];
    } else {
        int vb = blockIdx.x - FILLB4;
        for (int i = tid; i < IND * HIDD; i += 256) sW[i] = W0[i];
        __syncthreads();
        int j = tid & 127;
        int r0 = vb * 2 + (tid >> 7);
        for (int n = r0; n < Nn; n += G0B * 2) {
            float acc = 0.f;
            #pragma unroll
            for (int k = 0; k < IND; k++) acc = fmaf(x[n * IND + k], sW[k * HIDD + j], acc);
            g_h[n * HIDD + j] = acc * g_dinv[n];
        }
    }
}

// ---- SGEMM (f32x2, double-buffered): g_h = dinv_row*((act*a_row)@W + r), r = c@W ----
// BN (a,c) of previous layer computed inline from banked fp64 stats.
#define GBK 16
__global__ __launch_bounds__(256, 2) void gemm_kernel(const float* __restrict__ W,
                                                      const float* __restrict__ gw,
                                                      const float* __restrict__ be,
                                                      int prevLayer) {
    __shared__ float Ast[2][GBK * 132]; // transposed A chunk [k][row], pad 132
    __shared__ float Ws[2][GBK * 128];  // B chunk [k][j], pre-scaled by a[k]
    __shared__ float sa[HIDD], sc[HIDD], sdv[HIDD];
    __shared__ float rsm[8 * HIDD];
    __shared__ float rfin[HIDD];
    int tid = threadIdx.x;
    int blockRow = blockIdx.x * 128;
    if (tid < HIDD) {
        const double* bs = g_sumL + prevLayer * SBANK * HIDD;
        const double* bq = g_sqL + prevLayer * SBANK * HIDD;
        double su = 0.0, sq = 0.0;
        #pragma unroll
        for (int b = 0; b < SBANK; b++) {
            su += bs[b * HIDD + tid];
            sq += bq[b * HIDD + tid];
        }
        double mean = su * (1.0 / (double)Nn);
        double var = sq * (1.0 / (double)Nn) - mean * mean;
        float a = gw[tid] * rsqrtf((float)var + EPSv);
        sa[tid] = a;
        sc[tid] = be[tid] - (float)mean * a;
        int grow = blockRow + tid;
        sdv[tid] = (grow < Nn) ? g_dinv[grow] : 0.f;
    }
    __syncthreads();
    int tx = tid & 15, ty = tid >> 4;
    int ro = ty * 8, co = tx * 8;
    unsigned long long acc[8][4];
    #pragma unroll
    for (int i = 0; i < 8; i++)
        #pragma unroll
        for (int j = 0; j < 4; j++) acc[i][j] = 0ull;
    float rp0 = 0.f, rp1 = 0.f, rp2 = 0.f, rp3 = 0.f;

    // fixed per-thread load coordinates
    int arow0 = tid >> 2,         akq0 = tid & 3;
    int arow1 = (tid + 256) >> 2, akq1 = (tid + 256) & 3;
    int wkk0 = tid >> 5, wkk1 = (tid + 256) >> 5, wjq = tid & 31;
    int ag0 = blockRow + arow0, ag1 = blockRow + arow1;
    float4 ra0, ra1, rw0, rw1;

#define FETCH(kc) do { \
    ra0 = (ag0 < Nn) ? *(const float4*)&g_act[ag0 * 128 + (kc) + akq0 * 4] \
                     : make_float4(0.f, 0.f, 0.f, 0.f); \
    ra1 = (ag1 < Nn) ? *(const float4*)&g_act[ag1 * 128 + (kc) + akq1 * 4] \
                     : make_float4(0.f, 0.f, 0.f, 0.f); \
    rw0 = *(const float4*)&W[((kc) + wkk0) * 128 + wjq * 4]; \
    rw1 = *(const float4*)&W[((kc) + wkk1) * 128 + wjq * 4]; \
} while (0)

#define STORE(b, kc) do { \
    Ast[b][(akq0 * 4 + 0) * 132 + arow0] = ra0.x; \
    Ast[b][(akq0 * 4 + 1) * 132 + arow0] = ra0.y; \
    Ast[b][(akq0 * 4 + 2) * 132 + arow0] = ra0.z; \
    Ast[b][(akq0 * 4 + 3) * 132 + arow0] = ra0.w; \
    Ast[b][(akq1 * 4 + 0) * 132 + arow1] = ra1.x; \
    Ast[b][(akq1 * 4 + 1) * 132 + arow1] = ra1.y; \
    Ast[b][(akq1 * 4 + 2) * 132 + arow1] = ra1.z; \
    Ast[b][(akq1 * 4 + 3) * 132 + arow1] = ra1.w; \
    { int k = (kc) + wkk0; float ak = sa[k], ck = sc[k]; \
      rp0 = fmaf(ck, rw0.x, rp0); rp1 = fmaf(ck, rw0.y, rp1); \
      rp2 = fmaf(ck, rw0.z, rp2); rp3 = fmaf(ck, rw0.w, rp3); \
      *(float4*)&Ws[b][wkk0 * 128 + wjq * 4] = \
          make_float4(rw0.x * ak, rw0.y * ak, rw0.z * ak, rw0.w * ak); } \
    { int k = (kc) + wkk1; float ak = sa[k], ck = sc[k]; \
      rp0 = fmaf(ck, rw1.x, rp0); rp1 = fmaf(ck, rw1.y, rp1); \
      rp2 = fmaf(ck, rw1.z, rp2); rp3 = fmaf(ck, rw1.w, rp3); \
      *(float4*)&Ws[b][wkk1 * 128 + wjq * 4] = \
          make_float4(rw1.x * ak, rw1.y * ak, rw1.z * ak, rw1.w * ak); } \
} while (0)

    FETCH(0);
    STORE(0, 0);
    __syncthreads();
    #pragma unroll 2
    for (int c = 0; c < 8; c++) {
        int ib = c & 1;
        if (c < 7) FETCH((c + 1) * GBK);   // LDGs overlap with compute below
        #pragma unroll
        for (int kk = 0; kk < GBK; kk++) {
            float a[8];
            *(float4*)(a)     = *(float4*)&Ast[ib][kk * 132 + ro];
            *(float4*)(a + 4) = *(float4*)&Ast[ib][kk * 132 + ro + 4];
            ulonglong2 b01 = *(ulonglong2*)&Ws[ib][kk * 128 + co];
            ulonglong2 b23 = *(ulonglong2*)&Ws[ib][kk * 128 + co + 4];
            unsigned long long bp0 = b01.x, bp1 = b01.y, bp2 = b23.x, bp3 = b23.y;
            #pragma unroll
            for (int i2 = 0; i2 < 8; i2++) {
                unsigned long long ap = pack2_dup(a[i2]);
                ffma2(acc[i2][0], ap, bp0);
                ffma2(acc[i2][1], ap, bp1);
                ffma2(acc[i2][2], ap, bp2);
                ffma2(acc[i2][3], ap, bp3);
            }
        }
        if (c < 7) STORE(ib ^ 1, (c + 1) * GBK);
        __syncthreads();
    }
#undef FETCH
#undef STORE
    // reduce r across the 8 warps (jq fixed per thread)
    *(float4*)&rsm[(tid >> 5) * HIDD + wjq * 4] = make_float4(rp0, rp1, rp2, rp3);
    __syncthreads();
    if (tid < HIDD) {
        float s = 0.f;
        #pragma unroll
        for (int w = 0; w < 8; w++) s += rsm[w * HIDD + tid];
        rfin[tid] = s;
    }
    __syncthreads();
    float rl[8];
    *(float4*)(rl)     = *(float4*)&rfin[co];
    *(float4*)(rl + 4) = *(float4*)&rfin[co + 4];
    #pragma unroll
    for (int i2 = 0; i2 < 8; i2++) {
        int grow = blockRow + ro + i2;
        if (grow < Nn) {
            float dvr = sdv[ro + i2];
            float2 p0 = ull2f2(acc[i2][0]), p1 = ull2f2(acc[i2][1]);
            float2 p2 = ull2f2(acc[i2][2]), p3 = ull2f2(acc[i2][3]);
            *(float4*)&g_h[grow * 128 + co] =
                make_float4(dvr * (p0.x + rl[0]), dvr * (p0.y + rl[1]),
                            dvr * (p1.x + rl[2]), dvr * (p1.y + rl[3]));
            *(float4*)&g_h[grow * 128 + co + 4] =
                make_float4(dvr * (p2.x + rl[4]), dvr * (p2.y + rl[5]),
                            dvr * (p3.x + rl[6]), dvr * (p3.y + rl[7]));
        }
    }
}

// ------- aggregation + bias + rational + fused BN stats (banked fp64 atomics) ------
// 8 warps per block, one node per warp. Gather in unrolled groups of 8 independent
// float4 loads (MLP=8); padded lanes index the zero row (Nn) so they add 0.
// h rows are pre-scaled by dinv[src]; final result scaled by dinv[dst].
__global__ __launch_bounds__(256) void agg_kernel(const float* __restrict__ bvec,
                           const float* __restrict__ rat_num,
                           const float* __restrict__ rat_den,
                           const int* __restrict__ assign,
                           int layer) {
    __shared__ float s_num[CLUST * 6];
    __shared__ float s_den[CLUST * 4];
    __shared__ int   s_as[HIDD];
    __shared__ float s_b[HIDD];
    __shared__ float sp_sum[8 * HIDD];
    __shared__ float sp_sq[8 * HIDD];
    int tid = threadIdx.x;
    if (tid < CLUST * 6) s_num[tid] = rat_num[tid];
    if (tid < CLUST * 4) s_den[tid] = rat_den[tid];
    if (tid < HIDD) { s_as[tid] = assign[tid]; s_b[tid] = bvec[tid]; }
    __syncthreads();
    int lane = tid & 31;
    int wid = tid >> 5;
    int v = blockIdx.x * 8 + wid;
    float dv = g_dinv[v];
    int beg = g_rowptr[v], end = g_rowptr[v + 1];
    float4 acc = make_float4(0.f, 0.f, 0.f, 0.f);
    const unsigned FULL = 0xffffffffu;
    for (int base = beg; base < end; base += 32) {
        int my = (base + lane < end) ? g_csr[base + lane] : Nn;
        int m = min(32, end - base);
        for (int k = 0; k < m; k += 8) {
            int si[8];
            #pragma unroll
            for (int i = 0; i < 8; i++) si[i] = __shfl_sync(FULL, my, k + i);
            float4 hv[8];
            #pragma unroll
            for (int i = 0; i < 8; i++)
                hv[i] = *(const float4*)&g_h[si[i] * 128 + lane * 4];
            #pragma unroll
            for (int i = 0; i < 8; i++) {
                acc.x += hv[i].x;
                acc.y += hv[i].y;
                acc.z += hv[i].z;
                acc.w += hv[i].w;
            }
        }
    }
    {   // self term: + h'_v, then scale by dinv_v and add bias
        float4 hs = *(const float4*)&g_h[v * 128 + lane * 4];
        float4 bb = *(const float4*)&s_b[lane * 4];
        acc.x = fmaf(dv, acc.x + hs.x, bb.x);
        acc.y = fmaf(dv, acc.y + hs.y, bb.y);
        acc.z = fmaf(dv, acc.z + hs.z, bb.z);
        acc.w = fmaf(dv, acc.w + hs.w, bb.w);
    }
    float z[4] = {acc.x, acc.y, acc.z, acc.w};
    float out[4];
    #pragma unroll
    for (int c = 0; c < 4; c++) {
        int j = lane * 4 + c;
        int cl = s_as[j];
        const float* a = &s_num[cl * 6];
        const float* q = &s_den[cl * 4];
        float xx = z[c];
        float P = a[5];
        P = fmaf(P, xx, a[4]); P = fmaf(P, xx, a[3]); P = fmaf(P, xx, a[2]);
        P = fmaf(P, xx, a[1]); P = fmaf(P, xx, a[0]);
        float Q = q[3];
        Q = fmaf(Q, xx, q[2]); Q = fmaf(Q, xx, q[1]); Q = fmaf(Q, xx, q[0]);
        Q *= xx;
        out[c] = P / (1.0f + fabsf(Q));
        sp_sum[wid * HIDD + j] = out[c];
        sp_sq[wid * HIDD + j]  = out[c] * out[c];
    }
    *(float4*)&g_act[v * 128 + lane * 4] = make_float4(out[0], out[1], out[2], out[3]);
    __syncthreads();
    if (tid < HIDD) {
        float s = 0.f, q = 0.f;
        #pragma unroll
        for (int w = 0; w < 8; w++) {
            s += sp_sum[w * HIDD + tid];
            q += sp_sq[w * HIDD + tid];
        }
        int bank = layer * SBANK * HIDD + (blockIdx.x & (SBANK - 1)) * HIDD;
        atomicAdd(&g_sumL[bank + tid], (double)s);
        atomicAdd(&g_sqL[bank + tid], (double)q);
    }
}

// ------- fused pooling (inline layer-3 BN) + 3-stage MLP head, one block/graph -----
__global__ void poolmlp_kernel(const int* __restrict__ batch,
                               const float* __restrict__ gw, const float* __restrict__ be,
                               const float* __restrict__ HW1, const float* __restrict__ Hb1,
                               const float* __restrict__ HW2, const float* __restrict__ Hb2,
                               const float* __restrict__ HW3, const float* __restrict__ Hb3,
                               float* __restrict__ out) {
    __shared__ int s_se[2];
    __shared__ float part[256];
    __shared__ float sa[HIDD], sc[HIDD];
    __shared__ float srow[HIDD], srow2[HIDD];
    int tid = threadIdx.x; // 256
    int g = blockIdx.x;
    if (tid < 2) {
        int target = g + tid;
        int lo = 0, hi = Nn;
        while (lo < hi) { int mid = (lo + hi) >> 1; if (batch[mid] < target) lo = mid + 1; else hi = mid; }
        s_se[tid] = lo;
    }
    if (tid < HIDD) {
        const double* bs = g_sumL + 3 * SBANK * HIDD;
        const double* bq = g_sqL + 3 * SBANK * HIDD;
        double su = 0.0, sq = 0.0;
        #pragma unroll
        for (int b = 0; b < SBANK; b++) {
            su += bs[b * HIDD + tid];
            sq += bq[b * HIDD + tid];
        }
        double mean = su * (1.0 / (double)Nn);
        double var = sq * (1.0 / (double)Nn) - mean * mean;
        float a = gw[tid] * rsqrtf((float)var + EPSv);
        sa[tid] = a;
        sc[tid] = be[tid] - (float)mean * a;
    }
    __syncthreads();
    int s = s_se[0], e = s_se[1];
    int j = tid & 127, half = tid >> 7;
    {   // pooled mean, 2 row-groups x 4 accumulators
        float a0 = 0.f, a1 = 0.f, a2 = 0.f, a3 = 0.f;
        int n = s + half;
        for (; n + 6 < e; n += 8) {
            a0 += g_act[n * 128 + j];
            a1 += g_act[(n + 2) * 128 + j];
            a2 += g_act[(n + 4) * 128 + j];
            a3 += g_act[(n + 6) * 128 + j];
        }
        for (; n < e; n += 2) a0 += g_act[n * 128 + j];
        part[tid] = (a0 + a1) + (a2 + a3);
    }
    __syncthreads();
    if (tid < 128) {
        float m = part[tid] + part[tid + 128];
        srow[tid] = (e > s) ? fmaf(sa[tid], m / (float)(e - s), sc[tid]) : 0.f;
    }
    __syncthreads();
    {   // stage 1: split-k (half covers 64 of 128 k)
        int k0 = half * 64;
        float s0 = 0.f, s1 = 0.f;
        #pragma unroll
        for (int k = 0; k < 64; k += 2) {
            s0 = fmaf(srow[k0 + k],     HW1[(k0 + k) * 128 + j],     s0);
            s1 = fmaf(srow[k0 + k + 1], HW1[(k0 + k + 1) * 128 + j], s1);
        }
        part[tid] = s0 + s1;
    }
    __syncthreads();
    if (tid < 128) {
        float sg = part[tid] + part[tid + 128] + Hb1[tid];
        srow2[tid] = 0.5f * sg * (1.0f + erff(sg * 0.70710678118654752f));
    }
    __syncthreads();
    {   // stage 2
        int k0 = half * 64;
        float s0 = 0.f, s1 = 0.f;
        #pragma unroll
        for (int k = 0; k < 64; k += 2) {
            s0 = fmaf(srow2[k0 + k],     HW2[(k0 + k) * 128 + j],     s0);
            s1 = fmaf(srow2[k0 + k + 1], HW2[(k0 + k + 1) * 128 + j], s1);
        }
        part[tid] = s0 + s1;
    }
    __syncthreads();
    if (tid < 128) {
        float sg = part[tid] + part[tid + 128] + Hb2[tid];
        srow[tid] = 0.5f * sg * (1.0f + erff(sg * 0.70710678118654752f));
    }
    __syncthreads();
    if (tid < OUTD) {   // stage 3 (10 outputs)
        float s0 = Hb3[tid], s1 = 0.f, s2 = 0.f, s3 = 0.f;
        #pragma unroll
        for (int k = 0; k < 128; k += 4) {
            s0 = fmaf(srow[k],     HW3[(k)     * OUTD + tid], s0);
            s1 = fmaf(srow[k + 1], HW3[(k + 1) * OUTD + tid], s1);
            s2 = fmaf(srow[k + 2], HW3[(k + 2) * OUTD + tid], s2);
            s3 = fmaf(srow[k + 3], HW3[(k + 3) * OUTD + tid], s3);
        }
        out[g * OUTD + tid] = (s0 + s1) + (s2 + s3);
    }
}

// ---------------- host launch ----------------
extern "C" void kernel_launch(void* const* d_in, const int* in_sizes, int n_in,
                              void* d_out, int out_size) {
    (void)in_sizes; (void)n_in; (void)out_size;
    const float* x       = (const float*)d_in[0];
    const int*   ei      = (const int*)d_in[1];
    const int*   batch   = (const int*)d_in[2];
    const float* W[4]    = {(const float*)d_in[3],  (const float*)d_in[7],
                            (const float*)d_in[11], (const float*)d_in[15]};
    const float* bv[4]   = {(const float*)d_in[4],  (const float*)d_in[8],
                            (const float*)d_in[12], (const float*)d_in[16]};
    const float* gv[4]   = {(const float*)d_in[5],  (const float*)d_in[9],
                            (const float*)d_in[13], (const float*)d_in[17]};
    const float* bev[4]  = {(const float*)d_in[6],  (const float*)d_in[10],
                            (const float*)d_in[14], (const float*)d_in[18]};
    const float* rat_num = (const float*)d_in[19];
    const float* rat_den = (const float*)d_in[20];
    const int*   assign  = (const int*)d_in[21];
    const float* HW1     = (const float*)d_in[22];
    const float* Hb1     = (const float*)d_in[23];
    const float* HW2     = (const float*)d_in[24];
    const float* Hb2     = (const float*)d_in[25];
    const float* HW3     = (const float*)d_in[26];
    const float* Hb3     = (const float*)d_in[27];
    float* out = (float*)d_out;

    const int TB = 256;
    const int nBlocksAgg = Nn / 8;                   // 6250 (exact)
    const int nBlocksGemm = (Nn + 127) / 128;        // 391

    // ---- graph structure (per launch; state self-restoring across runs) ----
    hist_kernel<<<(Ee + TB - 1) / TB, TB>>>(ei);
    bsum_kernel<<<NB, 128>>>();
    rowptr_kernel<<<NB, 128>>>();                     // + stats-bank reset + dinv + cnt reset
    fill_gemm0_kernel<<<FILLB4 + G0B, TB>>>(ei, x, W[0]);

    // ---- layer 0 ----
    agg_kernel<<<nBlocksAgg, TB>>>(bv[0], rat_num, rat_den, assign, 0);

    // ---- layers 1..3 (BN folded into GEMM: inline (a,c), a-scale, +r, x dinv) ----
    for (int i = 1; i < 4; i++) {
        gemm_kernel<<<nBlocksGemm, 256>>>(W[i], gv[i - 1], bev[i - 1], i - 1);
        agg_kernel<<<nBlocksAgg, TB>>>(bv[i], rat_num, rat_den, assign, i);
    }

    // ---- fused pooling + MLP head ----
    poolmlp_kernel<<<Gg, 256>>>(batch, gv[3], bev[3], HW1, Hb1, HW2, Hb2, HW3, Hb3, out);
}